// round 1
// baseline (speedup 1.0000x reference)
#include <cuda_runtime.h>
#include <cuda_bf16.h>
#include <math.h>

// Problem constants
#define BATCH 8
#define SEQ   1024
#define DIN   1024
#define DOUT  1024
#define HEADS 16
#define DK    64

// Scratch for projected Q, K, V in [B, H, S, DK] layout.
// 8*16*1024*64 = 8,388,608 floats = 32 MB each.
__device__ float g_Q[BATCH * HEADS * SEQ * DK];
__device__ float g_K[BATCH * HEADS * SEQ * DK];
__device__ float g_V[BATCH * HEADS * SEQ * DK];

// ---------------------------------------------------------------------------
// Projection GEMM: out[b,h,s,dk] = (X[m,:] . W[n,:] + bias[n]) * scale
// X: [M=8192, K=1024] row-major (B*S flattened), W: [N=1024, K=1024] row-major.
// Classic 128x128 block tile, BK=16, 8x8 per-thread register tile, 256 threads.
// ---------------------------------------------------------------------------
#define BM 128
#define BN 128
#define BK 16
#define TM 8
#define TN 8

__global__ __launch_bounds__(256, 2)
void proj_kernel(const float* __restrict__ X,
                 const float* __restrict__ W,
                 const float* __restrict__ bias,
                 int which, float scale)
{
    __shared__ float As[BK][BM];
    __shared__ float Bs[BK][BN];

    float* out = (which == 0) ? g_Q : (which == 1) ? g_K : g_V;

    const int tid = threadIdx.x;
    const int tx = tid & 15;          // 0..15  -> column group
    const int ty = tid >> 4;          // 0..15  -> row group
    const int rowBase = blockIdx.y * BM;
    const int colBase = blockIdx.x * BN;

    // global-load coordinates: each thread loads 2 float4 per tile per matrix
    const int lr = tid >> 2;          // 0..63
    const int lc = (tid & 3) * 4;     // 0,4,8,12

    float acc[TM][TN];
    #pragma unroll
    for (int i = 0; i < TM; i++)
        #pragma unroll
        for (int j = 0; j < TN; j++)
            acc[i][j] = 0.f;

    for (int kt = 0; kt < DIN; kt += BK) {
        #pragma unroll
        for (int half = 0; half < 2; half++) {
            int r = lr + half * 64;
            float4 a = *(const float4*)&X[(size_t)(rowBase + r) * DIN + kt + lc];
            As[lc + 0][r] = a.x; As[lc + 1][r] = a.y;
            As[lc + 2][r] = a.z; As[lc + 3][r] = a.w;
            float4 w = *(const float4*)&W[(size_t)(colBase + r) * DIN + kt + lc];
            Bs[lc + 0][r] = w.x; Bs[lc + 1][r] = w.y;
            Bs[lc + 2][r] = w.z; Bs[lc + 3][r] = w.w;
        }
        __syncthreads();

        #pragma unroll
        for (int k = 0; k < BK; k++) {
            float ra[TM], rb[TN];
            #pragma unroll
            for (int i = 0; i < TM; i++) ra[i] = As[k][ty * TM + i];
            #pragma unroll
            for (int j = 0; j < TN; j++) rb[j] = Bs[k][tx * TN + j];
            #pragma unroll
            for (int i = 0; i < TM; i++)
                #pragma unroll
                for (int j = 0; j < TN; j++)
                    acc[i][j] = fmaf(ra[i], rb[j], acc[i][j]);
        }
        __syncthreads();
    }

    // Write permuted: m -> (b, s), n -> (h, dk); out[((b*H+h)*S + s)*DK + dk]
    #pragma unroll
    for (int i = 0; i < TM; i++) {
        int m = rowBase + ty * TM + i;
        int b = m >> 10;
        int s = m & 1023;
        #pragma unroll
        for (int j = 0; j < TN; j++) {
            int n = colBase + tx * TN + j;
            int h  = n >> 6;
            int dk = n & 63;
            size_t idx = (((size_t)(b * HEADS + h) * SEQ) + s) * DK + dk;
            out[idx] = (acc[i][j] + bias[n]) * scale;
        }
    }
}

// ---------------------------------------------------------------------------
// Flash-style attention: one query row per thread, online softmax.
// CTA = 128 threads = 128 query rows of one (b,h). K/V streamed in 16-row
// smem tiles; smem reads are pure broadcast (all threads read same address).
// Q rows were pre-scaled by 1/sqrt(DK) in the projection.
// ---------------------------------------------------------------------------
#define KV_TILE 16

__global__ __launch_bounds__(128)
void attn_kernel(float* __restrict__ out)
{
    const int bh = blockIdx.x;               // 0..127 = b*16 + h
    const int b = bh >> 4;
    const int h = bh & 15;
    const int r = blockIdx.y * 128 + threadIdx.x;   // query row in [0,1024)
    const int tid = threadIdx.x;

    const float* qp = g_Q + ((size_t)bh * SEQ + r) * DK;
    const float* kp = g_K + (size_t)bh * SEQ * DK;
    const float* vp = g_V + (size_t)bh * SEQ * DK;

    float q[DK];
    #pragma unroll
    for (int d = 0; d < DK; d += 4) {
        float4 v = *(const float4*)&qp[d];
        q[d] = v.x; q[d + 1] = v.y; q[d + 2] = v.z; q[d + 3] = v.w;
    }

    float o[DK];
    #pragma unroll
    for (int d = 0; d < DK; d++) o[d] = 0.f;
    float m = -1e30f, l = 0.f;

    __shared__ float Ks[KV_TILE][DK];
    __shared__ float Vs[KV_TILE][DK];

    for (int kt = 0; kt < SEQ; kt += KV_TILE) {
        __syncthreads();
        // 16*64 = 1024 floats = 256 float4 per matrix; 128 threads x 2 each.
        const float4* ksrc = (const float4*)(kp + (size_t)kt * DK);
        const float4* vsrc = (const float4*)(vp + (size_t)kt * DK);
        #pragma unroll
        for (int p = 0; p < 2; p++) {
            int idx4 = p * 128 + tid;
            ((float4*)Ks)[idx4] = ksrc[idx4];
            ((float4*)Vs)[idx4] = vsrc[idx4];
        }
        __syncthreads();

        // scores for this tile
        float s[KV_TILE];
        #pragma unroll
        for (int j = 0; j < KV_TILE; j++) {
            float a = 0.f;
            #pragma unroll
            for (int d = 0; d < DK; d++)
                a = fmaf(q[d], Ks[j][d], a);
            s[j] = a;
        }

        float tmax = m;
        #pragma unroll
        for (int j = 0; j < KV_TILE; j++) tmax = fmaxf(tmax, s[j]);
        float alpha = __expf(m - tmax);
        m = tmax;

        float psum = 0.f;
        #pragma unroll
        for (int j = 0; j < KV_TILE; j++) {
            s[j] = __expf(s[j] - tmax);
            psum += s[j];
        }
        l = l * alpha + psum;

        #pragma unroll
        for (int d = 0; d < DK; d++) {
            float a = o[d] * alpha;
            #pragma unroll
            for (int j = 0; j < KV_TILE; j++)
                a = fmaf(s[j], Vs[j][d], a);
            o[d] = a;
        }
    }

    // out[b, s*1024 + h*64 + d]
    const float inv = 1.f / l;
    float* op = out + ((size_t)b * SEQ + r) * DOUT + h * DK;
    #pragma unroll
    for (int d = 0; d < DK; d += 4) {
        float4 v = make_float4(o[d] * inv, o[d + 1] * inv,
                               o[d + 2] * inv, o[d + 3] * inv);
        *(float4*)&op[d] = v;
    }
}

// ---------------------------------------------------------------------------
// Launch
// ---------------------------------------------------------------------------
extern "C" void kernel_launch(void* const* d_in, const int* in_sizes, int n_in,
                              void* d_out, int out_size)
{
    const float* query = (const float*)d_in[0];
    const float* key_  = (const float*)d_in[1];
    const float* value = (const float*)d_in[2];
    const float* Wq    = (const float*)d_in[3];
    const float* bq    = (const float*)d_in[4];
    const float* Wk    = (const float*)d_in[5];
    const float* bk    = (const float*)d_in[6];
    const float* Wv    = (const float*)d_in[7];
    const float* bv    = (const float*)d_in[8];
    float* out = (float*)d_out;

    dim3 gproj(DOUT / BN, (BATCH * SEQ) / BM);   // (8, 64)
    const float qscale = 1.0f / 8.0f;            // 1/sqrt(DK)

    proj_kernel<<<gproj, 256>>>(query, Wq, bq, 0, qscale);
    proj_kernel<<<gproj, 256>>>(key_,  Wk, bk, 1, 1.0f);
    proj_kernel<<<gproj, 256>>>(value, Wv, bv, 2, 1.0f);

    dim3 gattn(BATCH * HEADS, SEQ / 128);        // (128, 8)
    attn_kernel<<<gattn, 128>>>(out);
}

// round 3
// speedup vs baseline: 1.6843x; 1.6843x over previous
#include <cuda_runtime.h>
#include <cuda_fp16.h>
#include <cstdint>
#include <math.h>

// Problem constants
#define BATCH 8
#define SEQ   1024
#define DIN   1024
#define DOUT  1024
#define HEADS 16
#define DK    64
#define MTOT  (BATCH * SEQ)     // 8192

// Scratch: projected Q, K, V in [B, H, S, DK] fp32 (32 MB each)
__device__ float g_Q[BATCH * HEADS * SEQ * DK];
__device__ float g_K[BATCH * HEADS * SEQ * DK];
__device__ float g_V[BATCH * HEADS * SEQ * DK];

// fp16 copies of inputs and weights
__device__ __half g_Xh[3][MTOT * DIN];     // 16 MB each
__device__ __half g_Wh[3][DOUT * DIN];     // 2 MB each

// ---------------------------------------------------------------------------
// fp32 -> fp16 convert (vectorized)
// ---------------------------------------------------------------------------
__global__ void cvt_fp16_kernel(const float4* __restrict__ src,
                                uint2* __restrict__ dst, int n4)
{
    int i = blockIdx.x * blockDim.x + threadIdx.x;
    if (i < n4) {
        float4 v = src[i];
        __half2 h0 = __floats2half2_rn(v.x, v.y);
        __half2 h1 = __floats2half2_rn(v.z, v.w);
        uint2 o;
        o.x = *(uint32_t*)&h0;
        o.y = *(uint32_t*)&h1;
        dst[i] = o;
    }
}

// ---------------------------------------------------------------------------
// PTX helpers (all plain sm_103 — no 'a'-gated features)
// ---------------------------------------------------------------------------
__device__ __forceinline__ uint32_t smem_u32(const void* p) {
    uint32_t a;
    asm("{ .reg .u64 t; cvta.to.shared.u64 t, %1; cvt.u32.u64 %0, t; }"
        : "=r"(a) : "l"(p));
    return a;
}

#define CP_ASYNC_16(dst_u32, src_ptr) \
    asm volatile("cp.async.cg.shared.global [%0], [%1], 16;" \
                 :: "r"(dst_u32), "l"(src_ptr))
#define CP_ASYNC_COMMIT() asm volatile("cp.async.commit_group;")
#define CP_ASYNC_WAIT_1() asm volatile("cp.async.wait_group 1;")
#define CP_ASYNC_WAIT_0() asm volatile("cp.async.wait_group 0;")

#define LDMATRIX_X4(r0, r1, r2, r3, addr) \
    asm volatile("ldmatrix.sync.aligned.m8n8.x4.shared.b16 {%0,%1,%2,%3}, [%4];" \
                 : "=r"(r0), "=r"(r1), "=r"(r2), "=r"(r3) : "r"(addr))

#define MMA_16816(c, a, b) \
    asm volatile("mma.sync.aligned.m16n8k16.row.col.f32.f16.f16.f32 " \
                 "{%0,%1,%2,%3}, {%4,%5,%6,%7}, {%8,%9}, {%0,%1,%2,%3};" \
                 : "+f"((c)[0]), "+f"((c)[1]), "+f"((c)[2]), "+f"((c)[3]) \
                 : "r"((a)[0]), "r"((a)[1]), "r"((a)[2]), "r"((a)[3]), \
                   "r"((b)[0]), "r"((b)[1]))

// ---------------------------------------------------------------------------
// Projection GEMM on mma.sync (fp16 in, fp32 accum):
//   out[b,h,s,dk] = (X[m,:] . W[n,:] + bias[n]) * scale
// CTA tile 128x128, 8 warps (2m x 4n) of 64x32, K-chunk = 64 halves.
// Smem: double-buffered A/B tiles, 128B rows, XOR-16B-chunk swizzle.
// Grid (DOUT/128, MTOT/128, 3), 256 threads.
// ---------------------------------------------------------------------------
#define KC 64
#define NCHUNK (DIN / KC)          // 16
#define TILE_BYTES 16384           // 128 rows x 128B
#define BUF_BYTES  (2 * TILE_BYTES)
#define PROJ_SMEM  (2 * BUF_BYTES) // 64 KB

__global__ __launch_bounds__(256)
void proj_mma_kernel(const float* __restrict__ bq,
                     const float* __restrict__ bk,
                     const float* __restrict__ bv)
{
    extern __shared__ char sm[];
    const uint32_t smb = smem_u32(sm);

    const int z = blockIdx.z;
    const __half* Xh = g_Xh[z];
    const __half* Wh = g_Wh[z];
    const float* bias = (z == 0) ? bq : (z == 1) ? bk : bv;
    float* out        = (z == 0) ? g_Q : (z == 1) ? g_K : g_V;
    const float scale = (z == 0) ? 0.125f : 1.0f;

    const int rowBase = blockIdx.y * 128;
    const int colBase = blockIdx.x * 128;
    const int tid  = threadIdx.x;
    const int wid  = tid >> 5;
    const int lane = tid & 31;
    const int warp_m = wid >> 2;      // 0..1
    const int warp_n = wid & 3;       // 0..3

    // copy mapping: idx = tid + t*256 -> (row = idx>>3, chunk = idx&7)
    // src halves offset: row*1024 + kc*64 + chunk*8 ; dst: row*128 + (chunk^(row&7))*16
    const int cp_r = tid >> 3;        // base row for t=0 (adds 32 per t)
    const int cp_c = tid & 7;

    float acc[4][4][4];
    #pragma unroll
    for (int mt = 0; mt < 4; mt++)
        #pragma unroll
        for (int nt = 0; nt < 4; nt++)
            #pragma unroll
            for (int k = 0; k < 4; k++)
                acc[mt][nt][k] = 0.f;

    // ldmatrix lane-address components
    const int rowA_l = (lane & 7) + ((lane >> 3) & 1) * 8;   // A row within 16
    const int koffA  = lane >> 4;                             // A k-chunk offset
    const int rowB_l = (lane & 7) + ((lane >> 4) & 1) * 8;   // B row within 16
    const int koffB  = (lane >> 3) & 1;
    const int swz    = lane & 7;                              // row&7 for both

    const uint32_t aRowAddr = smb + (uint32_t)(warp_m * 64 + rowA_l) * 128;
    const uint32_t bRowAddr = smb + TILE_BYTES + (uint32_t)(warp_n * 32 + rowB_l) * 128;

    // ---- copy helper (inlined twice) ----
    auto copy_chunk = [&](int kc, int s) {
        const uint32_t aBase = smb + s * BUF_BYTES;
        const uint32_t bBase = aBase + TILE_BYTES;
        #pragma unroll
        for (int t = 0; t < 4; t++) {
            int r = cp_r + t * 32;
            int c = cp_c;
            uint32_t dOff = (uint32_t)(r * 128 + ((c ^ (r & 7)) * 16));
            const __half* as = Xh + (size_t)(rowBase + r) * DIN + kc * KC + c * 8;
            CP_ASYNC_16(aBase + dOff, as);
            const __half* bs = Wh + (size_t)(colBase + r) * DIN + kc * KC + c * 8;
            CP_ASYNC_16(bBase + dOff, bs);
        }
        CP_ASYNC_COMMIT();
    };

    copy_chunk(0, 0);

    for (int kc = 0; kc < NCHUNK; kc++) {
        const int s = kc & 1;
        if (kc + 1 < NCHUNK) {
            copy_chunk(kc + 1, s ^ 1);
            CP_ASYNC_WAIT_1();
        } else {
            CP_ASYNC_WAIT_0();
        }
        __syncthreads();

        const uint32_t aB = aRowAddr + s * BUF_BYTES;
        const uint32_t bB = bRowAddr + s * BUF_BYTES;

        #pragma unroll
        for (int ks = 0; ks < 4; ks++) {
            uint32_t afrag[4][4];
            #pragma unroll
            for (int mt = 0; mt < 4; mt++) {
                uint32_t addr = aB + mt * 2048 + (uint32_t)(((ks * 2 + koffA) ^ swz) * 16);
                LDMATRIX_X4(afrag[mt][0], afrag[mt][1], afrag[mt][2], afrag[mt][3], addr);
            }
            uint32_t bfrag[4][2];
            #pragma unroll
            for (int np = 0; np < 2; np++) {
                uint32_t r0, r1, r2, r3;
                uint32_t addr = bB + np * 2048 + (uint32_t)(((ks * 2 + koffB) ^ swz) * 16);
                LDMATRIX_X4(r0, r1, r2, r3, addr);
                bfrag[np * 2][0] = r0; bfrag[np * 2][1] = r1;
                bfrag[np * 2 + 1][0] = r2; bfrag[np * 2 + 1][1] = r3;
            }
            #pragma unroll
            for (int mt = 0; mt < 4; mt++)
                #pragma unroll
                for (int nt = 0; nt < 4; nt++)
                    MMA_16816(acc[mt][nt], afrag[mt], bfrag[nt]);
        }
        __syncthreads();
    }

    // ---- epilogue: bias + scale, permuted store to [B,H,S,64] fp32 ----
    #pragma unroll
    for (int nt = 0; nt < 4; nt++) {
        const int n = colBase + warp_n * 32 + nt * 8 + (lane & 3) * 2;
        const int h = n >> 6;
        const int dk = n & 63;
        const float2 bv2 = *(const float2*)&bias[n];
        #pragma unroll
        for (int mt = 0; mt < 4; mt++) {
            const int m0 = rowBase + warp_m * 64 + mt * 16 + (lane >> 2);
            #pragma unroll
            for (int half = 0; half < 2; half++) {
                const int m = m0 + half * 8;
                const int b = m >> 10;
                const int sq = m & 1023;
                float2 v;
                v.x = (acc[mt][nt][half * 2 + 0] + bv2.x) * scale;
                v.y = (acc[mt][nt][half * 2 + 1] + bv2.y) * scale;
                *(float2*)&out[(((size_t)(b * HEADS + h) * SEQ) + sq) * DK + dk] = v;
            }
        }
    }
}

// ---------------------------------------------------------------------------
// Flash-style attention (unchanged): one query row per thread, online softmax.
// ---------------------------------------------------------------------------
#define KV_TILE 16

__global__ __launch_bounds__(128)
void attn_kernel(float* __restrict__ out)
{
    const int bh = blockIdx.x;
    const int b = bh >> 4;
    const int h = bh & 15;
    const int r = blockIdx.y * 128 + threadIdx.x;
    const int tid = threadIdx.x;

    const float* qp = g_Q + ((size_t)bh * SEQ + r) * DK;
    const float* kp = g_K + (size_t)bh * SEQ * DK;
    const float* vp = g_V + (size_t)bh * SEQ * DK;

    float q[DK];
    #pragma unroll
    for (int d = 0; d < DK; d += 4) {
        float4 v = *(const float4*)&qp[d];
        q[d] = v.x; q[d + 1] = v.y; q[d + 2] = v.z; q[d + 3] = v.w;
    }

    float o[DK];
    #pragma unroll
    for (int d = 0; d < DK; d++) o[d] = 0.f;
    float m = -1e30f, l = 0.f;

    __shared__ float Ks[KV_TILE][DK];
    __shared__ float Vs[KV_TILE][DK];

    for (int kt = 0; kt < SEQ; kt += KV_TILE) {
        __syncthreads();
        const float4* ksrc = (const float4*)(kp + (size_t)kt * DK);
        const float4* vsrc = (const float4*)(vp + (size_t)kt * DK);
        #pragma unroll
        for (int p = 0; p < 2; p++) {
            int idx4 = p * 128 + tid;
            ((float4*)Ks)[idx4] = ksrc[idx4];
            ((float4*)Vs)[idx4] = vsrc[idx4];
        }
        __syncthreads();

        float s[KV_TILE];
        #pragma unroll
        for (int j = 0; j < KV_TILE; j++) {
            float a = 0.f;
            #pragma unroll
            for (int d = 0; d < DK; d++)
                a = fmaf(q[d], Ks[j][d], a);
            s[j] = a;
        }

        float tmax = m;
        #pragma unroll
        for (int j = 0; j < KV_TILE; j++) tmax = fmaxf(tmax, s[j]);
        float alpha = __expf(m - tmax);
        m = tmax;

        float psum = 0.f;
        #pragma unroll
        for (int j = 0; j < KV_TILE; j++) {
            s[j] = __expf(s[j] - tmax);
            psum += s[j];
        }
        l = l * alpha + psum;

        #pragma unroll
        for (int d = 0; d < DK; d++) {
            float a = o[d] * alpha;
            #pragma unroll
            for (int j = 0; j < KV_TILE; j++)
                a = fmaf(s[j], Vs[j][d], a);
            o[d] = a;
        }
    }

    const float inv = 1.f / l;
    float* op = out + ((size_t)b * SEQ + r) * DOUT + h * DK;
    #pragma unroll
    for (int d = 0; d < DK; d += 4) {
        float4 v = make_float4(o[d] * inv, o[d + 1] * inv,
                               o[d + 2] * inv, o[d + 3] * inv);
        *(float4*)&op[d] = v;
    }
}

// ---------------------------------------------------------------------------
// Launch
// ---------------------------------------------------------------------------
extern "C" void kernel_launch(void* const* d_in, const int* in_sizes, int n_in,
                              void* d_out, int out_size)
{
    const float* query = (const float*)d_in[0];
    const float* key_  = (const float*)d_in[1];
    const float* value = (const float*)d_in[2];
    const float* Wq    = (const float*)d_in[3];
    const float* bq    = (const float*)d_in[4];
    const float* Wk    = (const float*)d_in[5];
    const float* bk    = (const float*)d_in[6];
    const float* Wv    = (const float*)d_in[7];
    const float* bv    = (const float*)d_in[8];
    float* out = (float*)d_out;

    // resolve device-global addresses
    __half* xh; __half* wh;
    cudaGetSymbolAddress((void**)&xh, g_Xh);
    cudaGetSymbolAddress((void**)&wh, g_Wh);

    const int xN4 = MTOT * DIN / 4;      // 2,097,152
    const int wN4 = DOUT * DIN / 4;      // 262,144
    const float* xs[3] = { query, key_, value };
    const float* ws[3] = { Wq, Wk, Wv };
    for (int z = 0; z < 3; z++) {
        cvt_fp16_kernel<<<(xN4 + 255) / 256, 256>>>(
            (const float4*)xs[z], (uint2*)(xh + (size_t)z * MTOT * DIN), xN4);
        cvt_fp16_kernel<<<(wN4 + 255) / 256, 256>>>(
            (const float4*)ws[z], (uint2*)(wh + (size_t)z * DOUT * DIN), wN4);
    }

    cudaFuncSetAttribute(proj_mma_kernel,
                         cudaFuncAttributeMaxDynamicSharedMemorySize, PROJ_SMEM);
    dim3 gproj(DOUT / 128, MTOT / 128, 3);   // (8, 64, 3)
    proj_mma_kernel<<<gproj, 256, PROJ_SMEM>>>(bq, bk, bv);

    dim3 gattn(BATCH * HEADS, SEQ / 128);    // (128, 8)
    attn_kernel<<<gattn, 128>>>(out);
}

// round 4
// speedup vs baseline: 11.1721x; 6.6331x over previous
#include <cuda_runtime.h>
#include <cuda_fp16.h>
#include <cstdint>
#include <math.h>

// Problem constants
#define BATCH 8
#define SEQ   1024
#define DIN   1024
#define DOUT  1024
#define HEADS 16
#define DK    64
#define MTOT  (BATCH * SEQ)     // 8192

// fp16 copies of inputs and weights (projection operands)
__device__ __align__(16) __half g_Xh[3][MTOT * DIN];     // 16 MB each
__device__ __align__(16) __half g_Wh[3][DOUT * DIN];     // 2 MB each

// Projected Q (pre-scaled by 1/8), K, V in [B, H, S, DK] fp16 (16 MB each)
__device__ __align__(16) __half g_Qh[BATCH * HEADS * SEQ * DK];
__device__ __align__(16) __half g_Kh[BATCH * HEADS * SEQ * DK];
__device__ __align__(16) __half g_Vh[BATCH * HEADS * SEQ * DK];

// ---------------------------------------------------------------------------
// fp32 -> fp16 convert (vectorized)
// ---------------------------------------------------------------------------
__global__ void cvt_fp16_kernel(const float4* __restrict__ src,
                                uint2* __restrict__ dst, int n4)
{
    int i = blockIdx.x * blockDim.x + threadIdx.x;
    if (i < n4) {
        float4 v = src[i];
        __half2 h0 = __floats2half2_rn(v.x, v.y);
        __half2 h1 = __floats2half2_rn(v.z, v.w);
        uint2 o;
        o.x = *(uint32_t*)&h0;
        o.y = *(uint32_t*)&h1;
        dst[i] = o;
    }
}

// ---------------------------------------------------------------------------
// PTX helpers (plain sm_103 features only)
// ---------------------------------------------------------------------------
__device__ __forceinline__ uint32_t smem_u32(const void* p) {
    uint32_t a;
    asm("{ .reg .u64 t; cvta.to.shared.u64 t, %1; cvt.u32.u64 %0, t; }"
        : "=r"(a) : "l"(p));
    return a;
}

#define CP_ASYNC_16(dst_u32, src_ptr) \
    asm volatile("cp.async.cg.shared.global [%0], [%1], 16;" \
                 :: "r"(dst_u32), "l"(src_ptr))
#define CP_ASYNC_COMMIT() asm volatile("cp.async.commit_group;")
#define CP_ASYNC_WAIT_1() asm volatile("cp.async.wait_group 1;")
#define CP_ASYNC_WAIT_0() asm volatile("cp.async.wait_group 0;")

#define LDMATRIX_X4(r0, r1, r2, r3, addr) \
    asm volatile("ldmatrix.sync.aligned.m8n8.x4.shared.b16 {%0,%1,%2,%3}, [%4];" \
                 : "=r"(r0), "=r"(r1), "=r"(r2), "=r"(r3) : "r"(addr))

#define LDMATRIX_X4_T(r0, r1, r2, r3, addr) \
    asm volatile("ldmatrix.sync.aligned.m8n8.x4.trans.shared.b16 {%0,%1,%2,%3}, [%4];" \
                 : "=r"(r0), "=r"(r1), "=r"(r2), "=r"(r3) : "r"(addr))

#define MMA_16816(c, a, b) \
    asm volatile("mma.sync.aligned.m16n8k16.row.col.f32.f16.f16.f32 " \
                 "{%0,%1,%2,%3}, {%4,%5,%6,%7}, {%8,%9}, {%0,%1,%2,%3};" \
                 : "+f"((c)[0]), "+f"((c)[1]), "+f"((c)[2]), "+f"((c)[3]) \
                 : "r"((a)[0]), "r"((a)[1]), "r"((a)[2]), "r"((a)[3]), \
                   "r"((b)[0]), "r"((b)[1]))

// ---------------------------------------------------------------------------
// Projection GEMM on mma.sync (fp16 in, fp32 accum, fp16 out):
//   out[b,h,s,dk] = half((X[m,:] . W[n,:] + bias[n]) * scale)
// CTA tile 128x128, 8 warps (2m x 4n) of 64x32, K-chunk = 64 halves.
// ---------------------------------------------------------------------------
#define KC 64
#define NCHUNK (DIN / KC)          // 16
#define TILE_BYTES 16384           // 128 rows x 128B
#define BUF_BYTES  (2 * TILE_BYTES)
#define PROJ_SMEM  (2 * BUF_BYTES) // 64 KB

__global__ __launch_bounds__(256)
void proj_mma_kernel(const float* __restrict__ bq,
                     const float* __restrict__ bk,
                     const float* __restrict__ bv)
{
    extern __shared__ char sm[];
    const uint32_t smb = smem_u32(sm);

    const int z = blockIdx.z;
    const __half* Xh = g_Xh[z];
    const __half* Wh = g_Wh[z];
    const float* bias = (z == 0) ? bq : (z == 1) ? bk : bv;
    __half* out       = (z == 0) ? g_Qh : (z == 1) ? g_Kh : g_Vh;
    const float scale = (z == 0) ? 0.125f : 1.0f;

    const int rowBase = blockIdx.y * 128;
    const int colBase = blockIdx.x * 128;
    const int tid  = threadIdx.x;
    const int wid  = tid >> 5;
    const int lane = tid & 31;
    const int warp_m = wid >> 2;
    const int warp_n = wid & 3;

    const int cp_r = tid >> 3;
    const int cp_c = tid & 7;

    float acc[4][4][4];
    #pragma unroll
    for (int mt = 0; mt < 4; mt++)
        #pragma unroll
        for (int nt = 0; nt < 4; nt++)
            #pragma unroll
            for (int k = 0; k < 4; k++)
                acc[mt][nt][k] = 0.f;

    const int rowA_l = (lane & 7) + ((lane >> 3) & 1) * 8;
    const int koffA  = lane >> 4;
    const int rowB_l = (lane & 7) + ((lane >> 4) & 1) * 8;
    const int koffB  = (lane >> 3) & 1;
    const int swz    = lane & 7;

    const uint32_t aRowAddr = smb + (uint32_t)(warp_m * 64 + rowA_l) * 128;
    const uint32_t bRowAddr = smb + TILE_BYTES + (uint32_t)(warp_n * 32 + rowB_l) * 128;

    auto copy_chunk = [&](int kc, int s) {
        const uint32_t aBase = smb + s * BUF_BYTES;
        const uint32_t bBase = aBase + TILE_BYTES;
        #pragma unroll
        for (int t = 0; t < 4; t++) {
            int r = cp_r + t * 32;
            int c = cp_c;
            uint32_t dOff = (uint32_t)(r * 128 + ((c ^ (r & 7)) * 16));
            const __half* as = Xh + (size_t)(rowBase + r) * DIN + kc * KC + c * 8;
            CP_ASYNC_16(aBase + dOff, as);
            const __half* bs = Wh + (size_t)(colBase + r) * DIN + kc * KC + c * 8;
            CP_ASYNC_16(bBase + dOff, bs);
        }
        CP_ASYNC_COMMIT();
    };

    copy_chunk(0, 0);

    for (int kc = 0; kc < NCHUNK; kc++) {
        const int s = kc & 1;
        if (kc + 1 < NCHUNK) {
            copy_chunk(kc + 1, s ^ 1);
            CP_ASYNC_WAIT_1();
        } else {
            CP_ASYNC_WAIT_0();
        }
        __syncthreads();

        const uint32_t aB = aRowAddr + s * BUF_BYTES;
        const uint32_t bB = bRowAddr + s * BUF_BYTES;

        #pragma unroll
        for (int ks = 0; ks < 4; ks++) {
            uint32_t afrag[4][4];
            #pragma unroll
            for (int mt = 0; mt < 4; mt++) {
                uint32_t addr = aB + mt * 2048 + (uint32_t)(((ks * 2 + koffA) ^ swz) * 16);
                LDMATRIX_X4(afrag[mt][0], afrag[mt][1], afrag[mt][2], afrag[mt][3], addr);
            }
            uint32_t bfrag[4][2];
            #pragma unroll
            for (int np = 0; np < 2; np++) {
                uint32_t r0, r1, r2, r3;
                uint32_t addr = bB + np * 2048 + (uint32_t)(((ks * 2 + koffB) ^ swz) * 16);
                LDMATRIX_X4(r0, r1, r2, r3, addr);
                bfrag[np * 2][0] = r0; bfrag[np * 2][1] = r1;
                bfrag[np * 2 + 1][0] = r2; bfrag[np * 2 + 1][1] = r3;
            }
            #pragma unroll
            for (int mt = 0; mt < 4; mt++)
                #pragma unroll
                for (int nt = 0; nt < 4; nt++)
                    MMA_16816(acc[mt][nt], afrag[mt], bfrag[nt]);
        }
        __syncthreads();
    }

    // epilogue: bias + scale, fp16 permuted store to [B,H,S,64]
    #pragma unroll
    for (int nt = 0; nt < 4; nt++) {
        const int n = colBase + warp_n * 32 + nt * 8 + (lane & 3) * 2;
        const int h = n >> 6;
        const int dk = n & 63;
        const float2 bv2 = *(const float2*)&bias[n];
        #pragma unroll
        for (int mt = 0; mt < 4; mt++) {
            const int m0 = rowBase + warp_m * 64 + mt * 16 + (lane >> 2);
            #pragma unroll
            for (int half_ = 0; half_ < 2; half_++) {
                const int m = m0 + half_ * 8;
                const int b = m >> 10;
                const int sq = m & 1023;
                __half2 hv = __floats2half2_rn(
                    (acc[mt][nt][half_ * 2 + 0] + bv2.x) * scale,
                    (acc[mt][nt][half_ * 2 + 1] + bv2.y) * scale);
                *(__half2*)&out[(((size_t)(b * HEADS + h) * SEQ) + sq) * DK + dk] = hv;
            }
        }
    }
}

// ---------------------------------------------------------------------------
// FlashAttention-2 on mma.sync: CTA = 128 q-rows of one (b,h), 4 warps x 32.
// K/V 64-row tiles double-buffered via cp.async. Q in registers.
// Smem: Qs 16KB | Ks[2] 8KB ea | Vs[2] 8KB ea = 48KB.
// ---------------------------------------------------------------------------
#define ATT_BC 64
#define QS_OFF 0
#define KS_OFF 16384
#define VS_OFF (16384 + 2 * 8192)
#define ATT_SMEM (16384 + 4 * 8192)   // 49152

__global__ __launch_bounds__(128)
void attn_mma_kernel(float* __restrict__ out)
{
    extern __shared__ char sm[];
    const uint32_t smb = smem_u32(sm);
    const int bh = blockIdx.x;
    const int b = bh >> 4;
    const int h = bh & 15;
    const int qbase = blockIdx.y * 128;
    const int tid = threadIdx.x;
    const int wid = tid >> 5;
    const int lane = tid & 31;

    const __half* Qp = g_Qh + ((size_t)bh * SEQ + qbase) * DK;
    const __half* Kp = g_Kh + (size_t)bh * SEQ * DK;
    const __half* Vp = g_Vh + (size_t)bh * SEQ * DK;

    // ---- async-load Q tile (128x64, swizzled) : group 0 ----
    #pragma unroll
    for (int t = 0; t < 8; t++) {
        int idx = t * 128 + tid;
        int r = idx >> 3, c = idx & 7;
        uint32_t dOff = (uint32_t)(QS_OFF + r * 128 + ((c ^ (r & 7)) * 16));
        CP_ASYNC_16(smb + dOff, Qp + (size_t)r * DK + c * 8);
    }
    CP_ASYNC_COMMIT();

    auto copy_kv = [&](int kt, int s) {
        const __half* kp = Kp + (size_t)kt * ATT_BC * DK;
        const __half* vp = Vp + (size_t)kt * ATT_BC * DK;
        const uint32_t kb = smb + KS_OFF + s * 8192;
        const uint32_t vb = smb + VS_OFF + s * 8192;
        #pragma unroll
        for (int t = 0; t < 4; t++) {
            int idx = t * 128 + tid;
            int r = idx >> 3, c = idx & 7;
            uint32_t off = (uint32_t)(r * 128 + ((c ^ (r & 7)) * 16));
            CP_ASYNC_16(kb + off, kp + (size_t)r * DK + c * 8);
            CP_ASYNC_16(vb + off, vp + (size_t)r * DK + c * 8);
        }
        CP_ASYNC_COMMIT();
    };

    copy_kv(0, 0);                 // group 1

    // ldmatrix lane components
    const int rowA_l = (lane & 7) + ((lane >> 3) & 1) * 8;
    const int koffA  = lane >> 4;
    const int rowB_l = (lane & 7) + ((lane >> 4) & 1) * 8;  // K (non-trans)
    const int koffB  = (lane >> 3) & 1;
    const int vRow   = (lane & 7) + ((lane >> 3) & 1) * 8;  // V (trans)
    const int vCoff  = (lane >> 4) & 1;
    const int swz    = lane & 7;

    // ---- Q fragments (wait for group 0; group 1 may still be pending) ----
    CP_ASYNC_WAIT_1();
    __syncthreads();
    uint32_t qfrag[2][4][4];
    #pragma unroll
    for (int mt = 0; mt < 2; mt++)
        #pragma unroll
        for (int ks = 0; ks < 4; ks++) {
            uint32_t addr = smb + QS_OFF +
                (uint32_t)(wid * 32 + mt * 16 + rowA_l) * 128 +
                (uint32_t)(((ks * 2 + koffA) ^ swz) * 16);
            LDMATRIX_X4(qfrag[mt][ks][0], qfrag[mt][ks][1],
                        qfrag[mt][ks][2], qfrag[mt][ks][3], addr);
        }

    // ---- state ----
    float of[2][8][4];
    #pragma unroll
    for (int mt = 0; mt < 2; mt++)
        #pragma unroll
        for (int j = 0; j < 8; j++)
            #pragma unroll
            for (int k = 0; k < 4; k++)
                of[mt][j][k] = 0.f;
    float m_st[2][2] = {{-1e30f, -1e30f}, {-1e30f, -1e30f}};
    float l_st[2][2] = {{0.f, 0.f}, {0.f, 0.f}};

    const int NT = SEQ / ATT_BC;     // 16

    for (int kt = 0; kt < NT; kt++) {
        const int s = kt & 1;
        if (kt + 1 < NT) {
            copy_kv(kt + 1, s ^ 1);
            CP_ASYNC_WAIT_1();
        } else {
            CP_ASYNC_WAIT_0();
        }
        __syncthreads();

        const uint32_t kBase = smb + KS_OFF + s * 8192;
        const uint32_t vBase = smb + VS_OFF + s * 8192;

        // ---- S = Q @ K^T  (128 x 64) ----
        float sf[2][8][4];
        #pragma unroll
        for (int mt = 0; mt < 2; mt++)
            #pragma unroll
            for (int j = 0; j < 8; j++)
                #pragma unroll
                for (int k = 0; k < 4; k++)
                    sf[mt][j][k] = 0.f;

        #pragma unroll
        for (int ks = 0; ks < 4; ks++) {
            uint32_t kb[8][2];
            #pragma unroll
            for (int np = 0; np < 4; np++) {
                uint32_t r0, r1, r2, r3;
                uint32_t addr = kBase + (uint32_t)(np * 16 + rowB_l) * 128 +
                                (uint32_t)(((ks * 2 + koffB) ^ swz) * 16);
                LDMATRIX_X4(r0, r1, r2, r3, addr);
                kb[np * 2][0] = r0; kb[np * 2][1] = r1;
                kb[np * 2 + 1][0] = r2; kb[np * 2 + 1][1] = r3;
            }
            #pragma unroll
            for (int mt = 0; mt < 2; mt++)
                #pragma unroll
                for (int j = 0; j < 8; j++)
                    MMA_16816(sf[mt][j], qfrag[mt][ks], kb[j]);
        }

        // ---- online softmax (per lane-quad rows) ----
        #pragma unroll
        for (int mt = 0; mt < 2; mt++) {
            float mx0 = -1e30f, mx1 = -1e30f;
            #pragma unroll
            for (int j = 0; j < 8; j++) {
                mx0 = fmaxf(mx0, fmaxf(sf[mt][j][0], sf[mt][j][1]));
                mx1 = fmaxf(mx1, fmaxf(sf[mt][j][2], sf[mt][j][3]));
            }
            mx0 = fmaxf(mx0, __shfl_xor_sync(0xffffffff, mx0, 1));
            mx0 = fmaxf(mx0, __shfl_xor_sync(0xffffffff, mx0, 2));
            mx1 = fmaxf(mx1, __shfl_xor_sync(0xffffffff, mx1, 1));
            mx1 = fmaxf(mx1, __shfl_xor_sync(0xffffffff, mx1, 2));

            float mn0 = fmaxf(m_st[mt][0], mx0);
            float mn1 = fmaxf(m_st[mt][1], mx1);
            float al0 = __expf(m_st[mt][0] - mn0);
            float al1 = __expf(m_st[mt][1] - mn1);
            m_st[mt][0] = mn0; m_st[mt][1] = mn1;

            float sum0 = 0.f, sum1 = 0.f;
            #pragma unroll
            for (int j = 0; j < 8; j++) {
                sf[mt][j][0] = __expf(sf[mt][j][0] - mn0);
                sf[mt][j][1] = __expf(sf[mt][j][1] - mn0);
                sf[mt][j][2] = __expf(sf[mt][j][2] - mn1);
                sf[mt][j][3] = __expf(sf[mt][j][3] - mn1);
                sum0 += sf[mt][j][0] + sf[mt][j][1];
                sum1 += sf[mt][j][2] + sf[mt][j][3];
            }
            sum0 += __shfl_xor_sync(0xffffffff, sum0, 1);
            sum0 += __shfl_xor_sync(0xffffffff, sum0, 2);
            sum1 += __shfl_xor_sync(0xffffffff, sum1, 1);
            sum1 += __shfl_xor_sync(0xffffffff, sum1, 2);
            l_st[mt][0] = l_st[mt][0] * al0 + sum0;
            l_st[mt][1] = l_st[mt][1] * al1 + sum1;

            #pragma unroll
            for (int j = 0; j < 8; j++) {
                of[mt][j][0] *= al0; of[mt][j][1] *= al0;
                of[mt][j][2] *= al1; of[mt][j][3] *= al1;
            }
        }

        // ---- O += P @ V ----
        #pragma unroll
        for (int kc = 0; kc < 4; kc++) {
            uint32_t vb[8][2];
            #pragma unroll
            for (int jp = 0; jp < 4; jp++) {
                uint32_t r0, r1, r2, r3;
                int cj = jp * 2 + vCoff;
                uint32_t addr = vBase + (uint32_t)(kc * 16 + vRow) * 128 +
                                (uint32_t)((cj ^ swz) * 16);
                LDMATRIX_X4_T(r0, r1, r2, r3, addr);
                vb[jp * 2][0] = r0; vb[jp * 2][1] = r1;
                vb[jp * 2 + 1][0] = r2; vb[jp * 2 + 1][1] = r3;
            }
            #pragma unroll
            for (int mt = 0; mt < 2; mt++) {
                uint32_t pa[4];
                __half2 p0 = __floats2half2_rn(sf[mt][kc * 2][0], sf[mt][kc * 2][1]);
                __half2 p1 = __floats2half2_rn(sf[mt][kc * 2][2], sf[mt][kc * 2][3]);
                __half2 p2 = __floats2half2_rn(sf[mt][kc * 2 + 1][0], sf[mt][kc * 2 + 1][1]);
                __half2 p3 = __floats2half2_rn(sf[mt][kc * 2 + 1][2], sf[mt][kc * 2 + 1][3]);
                pa[0] = *(uint32_t*)&p0;
                pa[1] = *(uint32_t*)&p1;
                pa[2] = *(uint32_t*)&p2;
                pa[3] = *(uint32_t*)&p3;
                #pragma unroll
                for (int j = 0; j < 8; j++)
                    MMA_16816(of[mt][j], pa, vb[j]);
            }
        }
        __syncthreads();
    }

    // ---- epilogue: normalize and store fp32 to out[b, sq*1024 + h*64 + dk] ----
    #pragma unroll
    for (int mt = 0; mt < 2; mt++) {
        const int r0 = qbase + wid * 32 + mt * 16 + (lane >> 2);
        const float inv0 = 1.f / l_st[mt][0];
        const float inv1 = 1.f / l_st[mt][1];
        #pragma unroll
        for (int j = 0; j < 8; j++) {
            const int dk = j * 8 + (lane & 3) * 2;
            float* p0 = out + ((size_t)b * SEQ + r0) * DOUT + h * DK + dk;
            float* p1 = out + ((size_t)b * SEQ + r0 + 8) * DOUT + h * DK + dk;
            *(float2*)p0 = make_float2(of[mt][j][0] * inv0, of[mt][j][1] * inv0);
            *(float2*)p1 = make_float2(of[mt][j][2] * inv1, of[mt][j][3] * inv1);
        }
    }
}

// ---------------------------------------------------------------------------
// Launch
// ---------------------------------------------------------------------------
extern "C" void kernel_launch(void* const* d_in, const int* in_sizes, int n_in,
                              void* d_out, int out_size)
{
    const float* query = (const float*)d_in[0];
    const float* key_  = (const float*)d_in[1];
    const float* value = (const float*)d_in[2];
    const float* Wq    = (const float*)d_in[3];
    const float* bq    = (const float*)d_in[4];
    const float* Wk    = (const float*)d_in[5];
    const float* bk    = (const float*)d_in[6];
    const float* Wv    = (const float*)d_in[7];
    const float* bv    = (const float*)d_in[8];
    float* out = (float*)d_out;

    __half* xh; __half* wh;
    cudaGetSymbolAddress((void**)&xh, g_Xh);
    cudaGetSymbolAddress((void**)&wh, g_Wh);

    const int xN4 = MTOT * DIN / 4;
    const int wN4 = DOUT * DIN / 4;
    const float* xs[3] = { query, key_, value };
    const float* ws[3] = { Wq, Wk, Wv };
    for (int z = 0; z < 3; z++) {
        cvt_fp16_kernel<<<(xN4 + 255) / 256, 256>>>(
            (const float4*)xs[z], (uint2*)(xh + (size_t)z * MTOT * DIN), xN4);
        cvt_fp16_kernel<<<(wN4 + 255) / 256, 256>>>(
            (const float4*)ws[z], (uint2*)(wh + (size_t)z * DOUT * DIN), wN4);
    }

    cudaFuncSetAttribute(proj_mma_kernel,
                         cudaFuncAttributeMaxDynamicSharedMemorySize, PROJ_SMEM);
    dim3 gproj(DOUT / 128, MTOT / 128, 3);
    proj_mma_kernel<<<gproj, 256, PROJ_SMEM>>>(bq, bk, bv);

    cudaFuncSetAttribute(attn_mma_kernel,
                         cudaFuncAttributeMaxDynamicSharedMemorySize, ATT_SMEM);
    dim3 gattn(BATCH * HEADS, SEQ / 128);
    attn_mma_kernel<<<gattn, 128, ATT_SMEM>>>(out);
}